// round 11
// baseline (speedup 1.0000x reference)
#include <cuda_runtime.h>
#include <cuda_bf16.h>
#include <math.h>

#define HS_B     8192
#define HS_P     32
#define HS_D     128
#define HS_GRID  888                // 148 SMs x 6 CTAs (best measured config)
#define HS_ITEMS (HS_B * 4)         // (row, 8-pos chunk) work items
#define FULLMASK 0xffffffffu

// Per-CTA {loss_sum, count} partials + completion counter (zero-init).
__device__ float2       g_hs_partial[HS_GRID];
__device__ unsigned int g_hs_ctr;

// ---------------------------------------------------------------------------
// Balanced persistent kernel. Item = (b, c): positions [8c, 8c+8) of row b.
// Node indices are fetched by uniform LDG (hardware broadcast: all lanes load
// the same address) instead of SHFL broadcasts; each 4-lane group loads its
// own code word directly instead of a warp ballot. 8 independent row-gathers
// per item; folding merge network (9 SHFL) leaves the complete dot for
// position k in lane group k = lane>>2; all 4 lanes of a group accumulate the
// same softplus and the final scalar divides the loss sum by 4.
// ---------------------------------------------------------------------------
__global__ __launch_bounds__(256, 6)
void hs_fused_kernel(const float* __restrict__ hidden,
                     const int*   __restrict__ target_path,
                     const int*   __restrict__ target_path_len,
                     const int*   __restrict__ target_code,
                     const float* __restrict__ embed_table,
                     float*       __restrict__ out) {
    const int tid  = threadIdx.x;
    const int warp = tid >> 5;
    const int lane = tid & 31;
    const int gw   = blockIdx.x * 8 + warp;
    const int GW   = gridDim.x * 8;

    const int j = lane >> 2;          // position index this lane group owns

    float accL = 0.0f;                // per-lane loss accumulator (4x counted)
    float accC = 0.0f;                // count accumulator (lane 0 only)

    for (int item = gw; item < HS_ITEMS; item += GW) {
        const int b    = item >> 2;
        const int base = (item & 3) * 8;
        const int L    = __ldg(&target_path_len[b]);
        if (base >= L) continue;      // warp-uniform skip
        const int n = min(8, L - base);
        const int rowoff = b * HS_P + base;

        // Node indices: uniform loads (HW broadcast), independent + MLP'd.
        int node[8];
        #pragma unroll
        for (int i = 0; i < 8; i++)
            node[i] = __ldg(&target_path[rowoff + i]);

        // Each 4-lane group loads its own code word (always in-bounds).
        const int code_j = __ldg(&target_code[rowoff + j]);

        // Hidden row: one float4 per lane (512 B, L2-resident).
        const float4 hv =
            reinterpret_cast<const float4*>(hidden + (size_t)b * HS_D)[lane];

        // Up to 8 independent embed-row gathers in flight.
        float d[8];
        #pragma unroll
        for (int i = 0; i < 8; i++) {
            d[i] = 0.0f;
            if (i < n) {
                const float4 e = reinterpret_cast<const float4*>(
                    embed_table + (size_t)node[i] * HS_D)[lane];
                d[i] = fmaf(e.x, hv.x, fmaf(e.y, hv.y,
                            fmaf(e.z, hv.z, e.w * hv.w)));
            }
        }

        // Folding merge network: 8 values -> 1 per 4-lane group.
        float e4[4];
        #pragma unroll
        for (int i = 0; i < 4; i++) {
            const float send = (lane & 16) ? d[i]     : d[i + 4];
            const float keep = (lane & 16) ? d[i + 4] : d[i];
            e4[i] = keep + __shfl_xor_sync(FULLMASK, send, 16);
        }
        float f2[2];
        #pragma unroll
        for (int i = 0; i < 2; i++) {
            const float send = (lane & 8) ? e4[i]     : e4[i + 2];
            const float keep = (lane & 8) ? e4[i + 2] : e4[i];
            f2[i] = keep + __shfl_xor_sync(FULLMASK, send, 8);
        }
        {
            const float send = (lane & 4) ? f2[0] : f2[1];
            const float keep = (lane & 4) ? f2[1] : f2[0];
            f2[0] = keep + __shfl_xor_sync(FULLMASK, send, 4);
        }
        float g = f2[0];
        g += __shfl_xor_sync(FULLMASK, g, 2);
        g += __shfl_xor_sync(FULLMASK, g, 1);
        // Lane group k = lane>>2 holds the complete dot for position k.

        if (j < n) {
            const float x = code_j ? g : -g;
            accL += __logf(1.0f + __expf(-x));   // -log(sigmoid(x)), 4x counted
        }
        if (lane == 0) accC += (float)n;
    }

    // Warp-level reduce of per-lane accumulators (once, after the loop).
    #pragma unroll
    for (int off = 16; off > 0; off >>= 1) {
        accL += __shfl_xor_sync(FULLMASK, accL, off);
        accC += __shfl_xor_sync(FULLMASK, accC, off);
    }

    __shared__ float2 swsum[8];
    if (lane == 0) swsum[warp] = make_float2(accL, accC);
    __syncthreads();

    __shared__ bool is_last;
    if (tid == 0) {
        float2 t = make_float2(0.0f, 0.0f);
        #pragma unroll
        for (int i = 0; i < 8; i++) { t.x += swsum[i].x; t.y += swsum[i].y; }
        g_hs_partial[blockIdx.x] = t;
        __threadfence();
        const unsigned prev = atomicAdd(&g_hs_ctr, 1u);
        is_last = (prev == (unsigned)(gridDim.x - 1));
    }
    __syncthreads();

    // Last CTA reduces the partials in fixed order and writes the scalar.
    if (is_last) {
        float ls = 0.0f, cs = 0.0f;
        #pragma unroll
        for (int i = 0; i < 4; i++) {
            const int k = tid + i * 256;
            if (k < HS_GRID) {
                const float2 v = __ldcg(&g_hs_partial[k]);
                ls += v.x;
                cs += v.y;
            }
        }
        #pragma unroll
        for (int off = 16; off > 0; off >>= 1) {
            ls += __shfl_xor_sync(FULLMASK, ls, off);
            cs += __shfl_xor_sync(FULLMASK, cs, off);
        }
        __shared__ float sl[8], sc[8];
        if (lane == 0) { sl[warp] = ls; sc[warp] = cs; }
        __syncthreads();
        if (tid == 0) {
            float tl = 0.0f, tc = 0.0f;
            #pragma unroll
            for (int i = 0; i < 8; i++) { tl += sl[i]; tc += sc[i]; }
            // Loss sum is 4x-counted (all 4 lanes of each group accumulated).
            out[0] = (float)(((double)tl * 0.25) / (double)tc);
            g_hs_ctr = 0;   // reset for next graph replay
        }
    }
}

// ---------------------------------------------------------------------------
// Inputs (metadata order): hidden_ f32[B,D], target i32[B] (unused),
// target_path i32[B,P], target_path_len i32[B], target_code i32[B,P],
// embed_table f32[V,D].  Output: f32 scalar.
// ---------------------------------------------------------------------------
extern "C" void kernel_launch(void* const* d_in, const int* in_sizes, int n_in,
                              void* d_out, int out_size) {
    const float* hidden      = (const float*)d_in[0];
    const int*   target_path = (const int*)  d_in[2];
    const int*   path_len    = (const int*)  d_in[3];
    const int*   target_code = (const int*)  d_in[4];
    const float* embed_table = (const float*)d_in[5];
    float*       out         = (float*)d_out;

    hs_fused_kernel<<<HS_GRID, 256>>>(hidden, target_path, path_len,
                                      target_code, embed_table, out);
}